// round 3
// baseline (speedup 1.0000x reference)
#include <cuda_runtime.h>
#include <math.h>

// Problem constants
#define Hd 1024
#define Vd 4096
#define Bd 64
#define Td 512
#define BT (Bd*Td)       // 32768
#define NTILES 16        // 1024/64 output col tiles for step GEMM
#define KSPLIT 8         // K splits for step GEMM

// Scratch (device globals; no runtime allocation)
__device__ float g_abase[(size_t)BT*Hd];                 // (t,b,h) pre-activation x_emb + b
__device__ float g_hs[(size_t)BT*Hd];                    // (t,b,h) hidden states
__device__ float g_part[NTILES*KSPLIT*4096];             // split-K partials (per 64x64 tile)
__device__ int   g_cnt[Td*NTILES];                       // zero-init; self-resetting

// ---------------------------------------------------------------------------
// K1: embedding gather + bias  a_base[(t*B+b), :] = wxh[X[b,t], :] + bvec
// grid: BT blocks x 256 threads, one float4/thread
// ---------------------------------------------------------------------------
__global__ void embed_kernel(const int* __restrict__ X,
                             const float* __restrict__ wxh,
                             const float* __restrict__ bvec) {
    int r = blockIdx.x;            // r = t*B + b
    int t = r >> 6;
    int b = r & 63;
    int row = X[b * Td + t];
    const float4* src = (const float4*)(wxh + (size_t)row * Hd);
    const float4* bb  = (const float4*)bvec;
    float4* dst = (float4*)(g_abase + (size_t)r * Hd);
    int i = threadIdx.x;           // 256 = H/4
    float4 v = src[i];
    float4 w = bb[i];
    v.x += w.x; v.y += w.y; v.z += w.z; v.w += w.w;
    dst[i] = v;
}

// ---------------------------------------------------------------------------
// K2: step 0  h_0 = tanh(a_base[0])
// ---------------------------------------------------------------------------
__global__ void step0_kernel() {
    int i = blockIdx.x * blockDim.x + threadIdx.x;   // B*H = 65536
    g_hs[i] = tanhf(g_abase[i]);
}

// ---------------------------------------------------------------------------
// K3: recurrence step t >= 1.
// h_t[b,j] = tanh(a_base[t,b,j] + sum_k h_{t-1}[b,k] * Whh[j,k])
// grid: (NTILES=16, KSPLIT=8) blocks, 256 threads.
// Each block computes a 64x64 partial over K=128, stores deterministically into
// g_part; last block per N-tile (atomic counter) sums the 8 partials in fixed
// order, adds a_base, applies tanh, writes g_hs. Counter self-resets to 0.
// ---------------------------------------------------------------------------
__global__ void step_kernel(const float* __restrict__ whh, int t) {
    __shared__ float A_s[16][68];
    __shared__ float W_s[16][68];
    const int ntile = blockIdx.x;
    const int ks    = blockIdx.y;
    const int j0    = ntile * 64;
    const int tid   = threadIdx.x;
    const int tx    = tid & 15;
    const int ty    = tid >> 4;

    const float* hprev = g_hs + (size_t)(t - 1) * Bd * Hd;

    float acc[4][4];
    #pragma unroll
    for (int i = 0; i < 4; i++)
        #pragma unroll
        for (int j = 0; j < 4; j++) acc[i][j] = 0.0f;

    const int lrow = tid >> 2;         // 0..63
    const int lk4  = (tid & 3) * 4;    // 0,4,8,12

    for (int kc = 0; kc < 8; ++kc) {
        int k0 = ks * 128 + kc * 16;
        float4 av = *(const float4*)(hprev + (size_t)lrow * Hd + k0 + lk4);
        float4 wv = *(const float4*)(whh + (size_t)(j0 + lrow) * Hd + k0 + lk4);
        __syncthreads();
        A_s[lk4 + 0][lrow] = av.x; A_s[lk4 + 1][lrow] = av.y;
        A_s[lk4 + 2][lrow] = av.z; A_s[lk4 + 3][lrow] = av.w;
        W_s[lk4 + 0][lrow] = wv.x; W_s[lk4 + 1][lrow] = wv.y;
        W_s[lk4 + 2][lrow] = wv.z; W_s[lk4 + 3][lrow] = wv.w;
        __syncthreads();
        #pragma unroll
        for (int kk = 0; kk < 16; ++kk) {
            float4 af = *(const float4*)&A_s[kk][ty * 4];
            float4 wf = *(const float4*)&W_s[kk][tx * 4];
            float a[4] = {af.x, af.y, af.z, af.w};
            float w[4] = {wf.x, wf.y, wf.z, wf.w};
            #pragma unroll
            for (int i = 0; i < 4; i++)
                #pragma unroll
                for (int j = 0; j < 4; j++)
                    acc[i][j] = fmaf(a[i], w[j], acc[i][j]);
        }
    }

    // deterministic partial store (no fp atomics)
    float* pbase = g_part + (ntile * KSPLIT + ks) * 4096;
    #pragma unroll
    for (int i = 0; i < 4; i++) {
        int b = ty * 4 + i;
        float4 v = make_float4(acc[i][0], acc[i][1], acc[i][2], acc[i][3]);
        *(float4*)&pbase[b * 64 + tx * 4] = v;
    }
    __threadfence();
    __syncthreads();

    __shared__ int s_last;
    if (tid == 0) {
        int prev = atomicAdd(&g_cnt[t * NTILES + ntile], 1);
        s_last = (prev == KSPLIT - 1) ? 1 : 0;
    }
    __syncthreads();

    if (s_last) {
        __threadfence();   // acquire side
        const float* acc_g = g_abase + (size_t)t * Bd * Hd;
        float* hout = g_hs + (size_t)t * Bd * Hd;
        const float* p0 = g_part + ntile * KSPLIT * 4096;
        for (int e = tid; e < 4096; e += 256) {
            int b  = e >> 6;
            int jj = e & 63;
            float sum = __ldcg(&acc_g[b * Hd + j0 + jj]);
            #pragma unroll
            for (int s = 0; s < KSPLIT; s++)
                sum += __ldcg(&p0[s * 4096 + e]);
            hout[b * Hd + j0 + jj] = tanhf(sum);
        }
        if (tid == 0) g_cnt[t * NTILES + ntile] = 0;  // self-reset for replay
    }
}

// ---------------------------------------------------------------------------
// K4: big output GEMM  z[r, v] = sum_k Hs[r, k] * Wvh[v, k] + c[v]
// written directly into outs region with row remap r=(t*B+b) -> (b*T+t)
// BM=128, BN=128, TK=16, 256 threads, 8x8 microtile.
// ---------------------------------------------------------------------------
__global__ void vh_gemm_kernel(const float* __restrict__ wvh,
                               const float* __restrict__ cvec,
                               float* __restrict__ outp) {
    __shared__ float A_s[16][132];
    __shared__ float B_s[16][132];
    const int v0 = blockIdx.x * 128;
    const int r0 = blockIdx.y * 128;
    const int tid = threadIdx.x;
    const int tx = tid & 15;
    const int ty = tid >> 4;

    float acc[8][8];
    #pragma unroll
    for (int i = 0; i < 8; i++)
        #pragma unroll
        for (int j = 0; j < 8; j++) acc[i][j] = 0.0f;

    const int lrow = tid >> 2;        // 0..63
    const int lk4  = (tid & 3) * 4;

    for (int kc = 0; kc < 64; ++kc) {
        int k0 = kc * 16;
        float4 a0 = *(const float4*)(g_hs + (size_t)(r0 + lrow) * Hd + k0 + lk4);
        float4 a1 = *(const float4*)(g_hs + (size_t)(r0 + lrow + 64) * Hd + k0 + lk4);
        float4 b0 = *(const float4*)(wvh + (size_t)(v0 + lrow) * Hd + k0 + lk4);
        float4 b1 = *(const float4*)(wvh + (size_t)(v0 + lrow + 64) * Hd + k0 + lk4);
        __syncthreads();
        A_s[lk4 + 0][lrow] = a0.x; A_s[lk4 + 1][lrow] = a0.y;
        A_s[lk4 + 2][lrow] = a0.z; A_s[lk4 + 3][lrow] = a0.w;
        A_s[lk4 + 0][lrow + 64] = a1.x; A_s[lk4 + 1][lrow + 64] = a1.y;
        A_s[lk4 + 2][lrow + 64] = a1.z; A_s[lk4 + 3][lrow + 64] = a1.w;
        B_s[lk4 + 0][lrow] = b0.x; B_s[lk4 + 1][lrow] = b0.y;
        B_s[lk4 + 2][lrow] = b0.z; B_s[lk4 + 3][lrow] = b0.w;
        B_s[lk4 + 0][lrow + 64] = b1.x; B_s[lk4 + 1][lrow + 64] = b1.y;
        B_s[lk4 + 2][lrow + 64] = b1.z; B_s[lk4 + 3][lrow + 64] = b1.w;
        __syncthreads();
        #pragma unroll
        for (int kk = 0; kk < 16; ++kk) {
            float4 af0 = *(const float4*)&A_s[kk][ty * 8];
            float4 af1 = *(const float4*)&A_s[kk][ty * 8 + 4];
            float4 wf0 = *(const float4*)&B_s[kk][tx * 8];
            float4 wf1 = *(const float4*)&B_s[kk][tx * 8 + 4];
            float a[8] = {af0.x, af0.y, af0.z, af0.w, af1.x, af1.y, af1.z, af1.w};
            float w[8] = {wf0.x, wf0.y, wf0.z, wf0.w, wf1.x, wf1.y, wf1.z, wf1.w};
            #pragma unroll
            for (int i = 0; i < 8; i++)
                #pragma unroll
                for (int j = 0; j < 8; j++)
                    acc[i][j] = fmaf(a[i], w[j], acc[i][j]);
        }
    }

    // epilogue: add c, remap row r=(t*B+b) -> out row (b*T + t), store
    float cl[8];
    #pragma unroll
    for (int j = 0; j < 8; j++) cl[j] = cvec[v0 + tx * 8 + j];

    #pragma unroll
    for (int i = 0; i < 8; i++) {
        int r = r0 + ty * 8 + i;
        int orow = (r & 63) * Td + (r >> 6);   // b*T + t
        float* op = outp + (size_t)orow * Vd + v0 + tx * 8;
        float4 o0 = make_float4(acc[i][0] + cl[0], acc[i][1] + cl[1],
                                acc[i][2] + cl[2], acc[i][3] + cl[3]);
        float4 o1 = make_float4(acc[i][4] + cl[4], acc[i][5] + cl[5],
                                acc[i][6] + cl[6], acc[i][7] + cl[7]);
        *(float4*)op = o0;
        *(float4*)(op + 4) = o1;
    }
}

// ---------------------------------------------------------------------------
// K5: in-place log_softmax over rows of 4096. One block (256 thr) per row.
// ---------------------------------------------------------------------------
__global__ void logsoftmax_kernel(float* __restrict__ outp) {
    float* row = outp + (size_t)blockIdx.x * Vd;
    const int tid = threadIdx.x;
    const int lane = tid & 31;
    const int wid = tid >> 5;
    __shared__ float sred[8];

    float4 v[4];
    float mx = -1e30f;
    #pragma unroll
    for (int i = 0; i < 4; i++) {
        v[i] = *(const float4*)(row + (i * 256 + tid) * 4);
        mx = fmaxf(mx, fmaxf(fmaxf(v[i].x, v[i].y), fmaxf(v[i].z, v[i].w)));
    }
    #pragma unroll
    for (int o = 16; o; o >>= 1) mx = fmaxf(mx, __shfl_xor_sync(0xffffffffu, mx, o));
    if (lane == 0) sred[wid] = mx;
    __syncthreads();
    float m2 = sred[lane & 7];
    #pragma unroll
    for (int o = 4; o; o >>= 1) m2 = fmaxf(m2, __shfl_xor_sync(0xffffffffu, m2, o));
    mx = m2;
    __syncthreads();

    float sum = 0.0f;
    #pragma unroll
    for (int i = 0; i < 4; i++) {
        sum += expf(v[i].x - mx) + expf(v[i].y - mx)
             + expf(v[i].z - mx) + expf(v[i].w - mx);
    }
    #pragma unroll
    for (int o = 16; o; o >>= 1) sum += __shfl_xor_sync(0xffffffffu, sum, o);
    if (lane == 0) sred[wid] = sum;
    __syncthreads();
    float s2 = sred[lane & 7];
    #pragma unroll
    for (int o = 4; o; o >>= 1) s2 += __shfl_xor_sync(0xffffffffu, s2, o);

    float lse = mx + logf(s2);
    #pragma unroll
    for (int i = 0; i < 4; i++) {
        v[i].x -= lse; v[i].y -= lse; v[i].z -= lse; v[i].w -= lse;
        *(float4*)(row + (i * 256 + tid) * 4) = v[i];
    }
}

// ---------------------------------------------------------------------------
// K6: hiddens transpose  outh[h, r] = g_hs[r, h]   (r = t*B+b)
// 32x32 smem tiles, block (32,8)
// ---------------------------------------------------------------------------
__global__ void transpose_kernel(float* __restrict__ outh) {
    __shared__ float tile[32][33];
    const int h0 = blockIdx.x * 32;
    const int r0 = blockIdx.y * 32;
    const int tx = threadIdx.x;
    const int ty = threadIdx.y;
    #pragma unroll
    for (int i = 0; i < 32; i += 8)
        tile[ty + i][tx] = g_hs[(size_t)(r0 + ty + i) * Hd + h0 + tx];
    __syncthreads();
    #pragma unroll
    for (int i = 0; i < 32; i += 8)
        outh[(size_t)(h0 + ty + i) * BT + r0 + tx] = tile[tx][ty + i];
}

// ---------------------------------------------------------------------------
extern "C" void kernel_launch(void* const* d_in, const int* in_sizes, int n_in,
                              void* d_out, int out_size) {
    const int*   X   = nullptr;
    const float* wxh = nullptr;
    const float* whh = nullptr;
    const float* wvh = nullptr;
    const float* bv  = nullptr;
    const float* cv  = nullptr;

    for (int i = 0; i < n_in; i++) {
        int s = in_sizes[i];
        if (s == BT && !X)            X   = (const int*)d_in[i];
        else if (s == Hd * Hd)        whh = (const float*)d_in[i];
        else if (s == Hd)             bv  = (const float*)d_in[i];
        else if (s == Vd)             cv  = (const float*)d_in[i];
        else if (s == Vd * Hd) {
            if (!wxh) wxh = (const float*)d_in[i];
            else      wvh = (const float*)d_in[i];
        }
    }

    float* outp = (float*)d_out;
    float* outs = outp;                       // (B, T, V) log-probs
    float* outh = outp + (size_t)BT * Vd;     // (H, T, B) hiddens

    // 1) embedding gather + bias
    embed_kernel<<<BT, 256>>>(X, wxh, bv);
    // 2) recurrence
    step0_kernel<<<(Bd * Hd) / 256, 256>>>();
    for (int t = 1; t < Td; t++)
        step_kernel<<<dim3(NTILES, KSPLIT), 256>>>(whh, t);
    // 3) output projection (writes z into outs with row remap)
    vh_gemm_kernel<<<dim3(Vd / 128, BT / 128), 256>>>(wvh, cv, outs);
    // 4) log_softmax in place
    logsoftmax_kernel<<<BT, 256>>>(outs);
    // 5) hiddens transpose
    transpose_kernel<<<dim3(Hd / 32, BT / 32), dim3(32, 8)>>>(outh);
}